// round 10
// baseline (speedup 1.0000x reference)
#include <cuda_runtime.h>
#include <cuda_bf16.h>

// Pendulum RK4 trajectory, N=200000, T=100. out[N][T][2] fp32.
// R2:  297us scalar strided stores (L1tex wavefront bound)
// R4:  46.9us smem-staged transpose stores (issue 77.9%)
// R8:  39.1us 16-step unroll (regs 64, occ 38.7%, issue 65.5%)
// R9:  39.6us unroll8+lb(256,5): regs 47, occ 44.6%, issue 67.8% -> NOT
//      issue-starved by occupancy; latency-bound on the serial
//      MUFU.SIN->FFMA chain (~96 cyc/step, issue density 0.36/warp).
// R10: ILP=2 — each thread integrates TWO independent particles, doubling
//      per-warp issue density. 8-slot chunks, warp owns 64 particles.

#define PEND_T 100
#define PEND_G 10.0f
#define ROWF2  10           // 8 slots + pad, 80B pitch (16B-aligned rows)
#define NWARPS 8

// One RK4 step on two independent pendulum states (shared dt triple).
__device__ __forceinline__ void rk4_step2(
    float& tA, float& wA, float cA,
    float& tB, float& wB, float cB,
    float4 d)
{
    const float dt = d.x, dt3 = d.y, dt8 = d.z;
    const float third = 1.0f / 3.0f;

    const float k1tA = wA,               k1tB = wB;
    const float k1wA = cA * __sinf(tA);
    const float k1wB = cB * __sinf(tB);

    const float y2tA = fmaf(dt3, k1tA, tA), y2tB = fmaf(dt3, k1tB, tB);
    const float y2wA = fmaf(dt3, k1wA, wA), y2wB = fmaf(dt3, k1wB, wB);
    const float k2tA = y2wA,             k2tB = y2wB;
    const float k2wA = cA * __sinf(y2tA);
    const float k2wB = cB * __sinf(y2tB);

    const float e3tA = fmaf(-third, k1tA, k2tA), e3tB = fmaf(-third, k1tB, k2tB);
    const float e3wA = fmaf(-third, k1wA, k2wA), e3wB = fmaf(-third, k1wB, k2wB);
    const float y3tA = fmaf(dt, e3tA, tA),       y3tB = fmaf(dt, e3tB, tB);
    const float y3wA = fmaf(dt, e3wA, wA),       y3wB = fmaf(dt, e3wB, wB);
    const float k3tA = y3wA,             k3tB = y3wB;
    const float k3wA = cA * __sinf(y3tA);
    const float k3wB = cB * __sinf(y3tB);

    const float e4tA = (k1tA - k2tA) + k3tA, e4tB = (k1tB - k2tB) + k3tB;
    const float e4wA = (k1wA - k2wA) + k3wA, e4wB = (k1wB - k2wB) + k3wB;
    const float y4tA = fmaf(dt, e4tA, tA),   y4tB = fmaf(dt, e4tB, tB);
    const float y4wA = fmaf(dt, e4wA, wA),   y4wB = fmaf(dt, e4wB, wB);
    const float k4tA = y4wA,             k4tB = y4wB;
    const float k4wA = cA * __sinf(y4tA);
    const float k4wB = cB * __sinf(y4tB);

    const float stA = fmaf(3.0f, k2tA + k3tA, k1tA) + k4tA;
    const float swA = fmaf(3.0f, k2wA + k3wA, k1wA) + k4wA;
    const float stB = fmaf(3.0f, k2tB + k3tB, k1tB) + k4tB;
    const float swB = fmaf(3.0f, k2wB + k3wB, k1wB) + k4wB;
    tA = fmaf(dt8, stA, tA);  wA = fmaf(dt8, swA, wA);
    tB = fmaf(dt8, stB, tB);  wB = fmaf(dt8, swB, wB);
}

// Flush one 8-slot chunk for 64 particles: 4 float4 per particle,
// 4 consecutive lanes cover one particle's 64B chunk (full sectors).
__device__ __forceinline__ void flush8(const float2 (* __restrict__ mybuf)[ROWF2],
                                       float4* __restrict__ out4,
                                       size_t rowbase, int lane, int base)
{
    __syncwarp();
    #pragma unroll
    for (int j = 0; j < 8; j++) {
        const int idx = j * 32 + lane;
        const int p   = idx >> 2;          // particle within warp (0..63)
        const int s4  = idx & 3;           // float4 slot within chunk
        const float4 v = *reinterpret_cast<const float4*>(&mybuf[p][s4 * 2]);
        out4[rowbase + (size_t)p * (PEND_T / 2) + (base >> 1) + s4] = v;
    }
    __syncwarp();
}

__global__ __launch_bounds__(256, 3) void pendulum_rk4_kernel(
    const float* __restrict__ t,
    const float* __restrict__ z0,
    const float* __restrict__ params,
    float* __restrict__ out,
    int n)
{
    __shared__ __align__(16) float4 sdt4[PEND_T - 1];        // {dt, dt/3, dt/8, -}
    __shared__ __align__(16) float2 buf[NWARPS][64][ROWF2];  // 40KB

    for (int j = threadIdx.x; j < PEND_T - 1; j += blockDim.x) {
        const float d = t[j + 1] - t[j];
        sdt4[j] = make_float4(d, d * (1.0f / 3.0f), d * 0.125f, 0.0f);
    }
    __syncthreads();

    const int warp = threadIdx.x >> 5;
    const int lane = threadIdx.x & 31;
    const int wb64 = (blockIdx.x * NWARPS + warp) * 64;      // first particle of warp
    if (wb64 >= n) return;          // n multiple of 64: whole warps only

    float2 (* __restrict__ mybuf)[ROWF2] = buf[warp];

    const int iA = wb64 + lane;
    const int iB = iA + 32;
    const float2 zA = reinterpret_cast<const float2*>(z0)[iA];
    const float2 zB = reinterpret_cast<const float2*>(z0)[iB];
    float tA = zA.x, wA = zA.y;
    float tB = zB.x, wB = zB.y;
    const float cA = -(PEND_G / params[iA]);
    const float cB = -(PEND_G / params[iB]);

    float4* __restrict__ out4 = reinterpret_cast<float4*>(out);
    const size_t rowbase = (size_t)wb64 * (PEND_T / 2);      // 50 float4/row

    // ---- chunk 0: slot 0 (initial state) + steps 1..7 ----
    mybuf[lane][0]      = make_float2(tA, wA);
    mybuf[lane + 32][0] = make_float2(tB, wB);
    #pragma unroll
    for (int k = 1; k < 8; k++) {
        rk4_step2(tA, wA, cA, tB, wB, cB, sdt4[k - 1]);
        mybuf[lane][k]      = make_float2(tA, wA);
        mybuf[lane + 32][k] = make_float2(tB, wB);
    }
    flush8(mybuf, out4, rowbase, lane, 0);

    // ---- chunks 1..11: 8 steps each ----
    #pragma unroll 1
    for (int c = 1; c < 12; c++) {
        const int base = c * 8;
        #pragma unroll
        for (int k = 0; k < 8; k++) {
            rk4_step2(tA, wA, cA, tB, wB, cB, sdt4[base - 1 + k]);
            mybuf[lane][k]      = make_float2(tA, wA);
            mybuf[lane + 32][k] = make_float2(tB, wB);
        }
        flush8(mybuf, out4, rowbase, lane, base);
    }

    // ---- tail: steps 96..99 (4 slots = 2 float4 per particle) ----
    #pragma unroll
    for (int k = 0; k < 4; k++) {
        rk4_step2(tA, wA, cA, tB, wB, cB, sdt4[95 + k]);
        mybuf[lane][k]      = make_float2(tA, wA);
        mybuf[lane + 32][k] = make_float2(tB, wB);
    }
    __syncwarp();
    #pragma unroll
    for (int j = 0; j < 4; j++) {
        const int idx = j * 32 + lane;
        const int p   = idx >> 1;          // 0..63
        const int s4  = idx & 1;
        const float4 v = *reinterpret_cast<const float4*>(&mybuf[p][s4 * 2]);
        out4[rowbase + (size_t)p * (PEND_T / 2) + 48 + s4] = v;
    }
}

extern "C" void kernel_launch(void* const* d_in, const int* in_sizes, int n_in,
                              void* d_out, int out_size)
{
    (void)n_in; (void)out_size;
    // d_in[0] = mini_batch (unused), d_in[1] = t, d_in[2] = z0, d_in[3] = params
    const float* t      = (const float*)d_in[1];
    const float* z0     = (const float*)d_in[2];
    const float* params = (const float*)d_in[3];
    float* out          = (float*)d_out;

    const int n = in_sizes[3];
    const int per_block = 64 * NWARPS;               // 512 particles/block
    const int blocks = (n + per_block - 1) / per_block;
    pendulum_rk4_kernel<<<blocks, 256>>>(t, z0, params, out, n);
}

// round 11
// speedup vs baseline: 1.0283x; 1.0283x over previous
#include <cuda_runtime.h>
#include <cuda_bf16.h>

// Pendulum RK4 trajectory, N=200000, T=100. out[N][T][2] fp32.
// R2:  297us scalar strided stores (L1tex wavefront bound)
// R4:  46.9us smem-staged transpose stores (issue 77.9%)
// R8:  39.1us 16-step unroll (regs 64, occ 38.7%, issue 65.5%)
// R9:  39.6us unroll8+lb(256,5) (regs 47, occ 44.6%, issue 67.8%)
// R10: 43.0us ILP2 @256thr lb(,3): density up but occ 27.7%, issue 59.9% —
//      concurrency loss (regs 78 + 391-block grid tail) ate the ILP gain.
// R11: ILP2 @128-thread blocks, lb(128,8) (64-reg budget, 32 warps/SM),
//      unroll 4 to fit the window. Grid back to 782 blocks.

#define PEND_T 100
#define PEND_G 10.0f
#define ROWF2  10           // 8 slots + pad, 80B pitch (16B-aligned rows)
#define NWARPS 4            // 128 threads

// One RK4 step on two independent pendulum states (shared dt triple).
__device__ __forceinline__ void rk4_step2(
    float& tA, float& wA, float cA,
    float& tB, float& wB, float cB,
    float4 d)
{
    const float dt = d.x, dt3 = d.y, dt8 = d.z;
    const float third = 1.0f / 3.0f;

    const float k1tA = wA,               k1tB = wB;
    const float k1wA = cA * __sinf(tA);
    const float k1wB = cB * __sinf(tB);

    const float y2tA = fmaf(dt3, k1tA, tA), y2tB = fmaf(dt3, k1tB, tB);
    const float y2wA = fmaf(dt3, k1wA, wA), y2wB = fmaf(dt3, k1wB, wB);
    const float k2tA = y2wA,             k2tB = y2wB;
    const float k2wA = cA * __sinf(y2tA);
    const float k2wB = cB * __sinf(y2tB);

    const float e3tA = fmaf(-third, k1tA, k2tA), e3tB = fmaf(-third, k1tB, k2tB);
    const float e3wA = fmaf(-third, k1wA, k2wA), e3wB = fmaf(-third, k1wB, k2wB);
    const float y3tA = fmaf(dt, e3tA, tA),       y3tB = fmaf(dt, e3tB, tB);
    const float y3wA = fmaf(dt, e3wA, wA),       y3wB = fmaf(dt, e3wB, wB);
    const float k3tA = y3wA,             k3tB = y3wB;
    const float k3wA = cA * __sinf(y3tA);
    const float k3wB = cB * __sinf(y3tB);

    const float e4tA = (k1tA - k2tA) + k3tA, e4tB = (k1tB - k2tB) + k3tB;
    const float e4wA = (k1wA - k2wA) + k3wA, e4wB = (k1wB - k2wB) + k3wB;
    const float y4tA = fmaf(dt, e4tA, tA),   y4tB = fmaf(dt, e4tB, tB);
    const float y4wA = fmaf(dt, e4wA, wA),   y4wB = fmaf(dt, e4wB, wB);
    const float k4tA = y4wA,             k4tB = y4wB;
    const float k4wA = cA * __sinf(y4tA);
    const float k4wB = cB * __sinf(y4tB);

    const float stA = fmaf(3.0f, k2tA + k3tA, k1tA) + k4tA;
    const float swA = fmaf(3.0f, k2wA + k3wA, k1wA) + k4wA;
    const float stB = fmaf(3.0f, k2tB + k3tB, k1tB) + k4tB;
    const float swB = fmaf(3.0f, k2wB + k3wB, k1wB) + k4wB;
    tA = fmaf(dt8, stA, tA);  wA = fmaf(dt8, swA, wA);
    tB = fmaf(dt8, stB, tB);  wB = fmaf(dt8, swB, wB);
}

// Flush one 8-slot chunk for 64 particles: 4 float4 per particle,
// 4 consecutive lanes cover one particle's 64B chunk (full 32B sectors).
__device__ __forceinline__ void flush8(const float2 (* __restrict__ mybuf)[ROWF2],
                                       float4* __restrict__ out4,
                                       size_t rowbase, int lane, int base)
{
    __syncwarp();
    #pragma unroll
    for (int j = 0; j < 8; j++) {
        const int idx = j * 32 + lane;
        const int p   = idx >> 2;          // particle within warp (0..63)
        const int s4  = idx & 3;           // float4 slot within chunk
        const float4 v = *reinterpret_cast<const float4*>(&mybuf[p][s4 * 2]);
        out4[rowbase + (size_t)p * (PEND_T / 2) + (base >> 1) + s4] = v;
    }
    __syncwarp();
}

__global__ __launch_bounds__(128, 8) void pendulum_rk4_kernel(
    const float* __restrict__ t,
    const float* __restrict__ z0,
    const float* __restrict__ params,
    float* __restrict__ out,
    int n)
{
    __shared__ __align__(16) float4 sdt4[PEND_T - 1];        // {dt, dt/3, dt/8, -}
    __shared__ __align__(16) float2 buf[NWARPS][64][ROWF2];  // 20KB

    for (int j = threadIdx.x; j < PEND_T - 1; j += blockDim.x) {
        const float d = t[j + 1] - t[j];
        sdt4[j] = make_float4(d, d * (1.0f / 3.0f), d * 0.125f, 0.0f);
    }
    __syncthreads();

    const int warp = threadIdx.x >> 5;
    const int lane = threadIdx.x & 31;
    const int wb64 = (blockIdx.x * NWARPS + warp) * 64;      // first particle of warp
    if (wb64 >= n) return;          // n multiple of 64: whole warps only

    float2 (* __restrict__ mybuf)[ROWF2] = buf[warp];

    const int iA = wb64 + lane;
    const int iB = iA + 32;
    const float2 zA = reinterpret_cast<const float2*>(z0)[iA];
    const float2 zB = reinterpret_cast<const float2*>(z0)[iB];
    float tA = zA.x, wA = zA.y;
    float tB = zB.x, wB = zB.y;
    const float cA = -(PEND_G / params[iA]);
    const float cB = -(PEND_G / params[iB]);

    float4* __restrict__ out4 = reinterpret_cast<float4*>(out);
    const size_t rowbase = (size_t)wb64 * (PEND_T / 2);      // 50 float4/row

    // ---- chunk 0: slot 0 (initial state) + steps 1..7 ----
    mybuf[lane][0]      = make_float2(tA, wA);
    mybuf[lane + 32][0] = make_float2(tB, wB);
    #pragma unroll 4
    for (int k = 1; k < 8; k++) {
        rk4_step2(tA, wA, cA, tB, wB, cB, sdt4[k - 1]);
        mybuf[lane][k]      = make_float2(tA, wA);
        mybuf[lane + 32][k] = make_float2(tB, wB);
    }
    flush8(mybuf, out4, rowbase, lane, 0);

    // ---- chunks 1..11: 8 steps each ----
    #pragma unroll 1
    for (int c = 1; c < 12; c++) {
        const int base = c * 8;
        #pragma unroll 4
        for (int k = 0; k < 8; k++) {
            rk4_step2(tA, wA, cA, tB, wB, cB, sdt4[base - 1 + k]);
            mybuf[lane][k]      = make_float2(tA, wA);
            mybuf[lane + 32][k] = make_float2(tB, wB);
        }
        flush8(mybuf, out4, rowbase, lane, base);
    }

    // ---- tail: steps 96..99 (4 slots = 2 float4 per particle) ----
    #pragma unroll
    for (int k = 0; k < 4; k++) {
        rk4_step2(tA, wA, cA, tB, wB, cB, sdt4[95 + k]);
        mybuf[lane][k]      = make_float2(tA, wA);
        mybuf[lane + 32][k] = make_float2(tB, wB);
    }
    __syncwarp();
    #pragma unroll
    for (int j = 0; j < 4; j++) {
        const int idx = j * 32 + lane;
        const int p   = idx >> 1;          // 0..63
        const int s4  = idx & 1;
        const float4 v = *reinterpret_cast<const float4*>(&mybuf[p][s4 * 2]);
        out4[rowbase + (size_t)p * (PEND_T / 2) + 48 + s4] = v;
    }
}

extern "C" void kernel_launch(void* const* d_in, const int* in_sizes, int n_in,
                              void* d_out, int out_size)
{
    (void)n_in; (void)out_size;
    // d_in[0] = mini_batch (unused), d_in[1] = t, d_in[2] = z0, d_in[3] = params
    const float* t      = (const float*)d_in[1];
    const float* z0     = (const float*)d_in[2];
    const float* params = (const float*)d_in[3];
    float* out          = (float*)d_out;

    const int n = in_sizes[3];
    const int per_block = 64 * NWARPS;               // 256 particles/block
    const int blocks = (n + per_block - 1) / per_block;
    pendulum_rk4_kernel<<<blocks, 128>>>(t, z0, params, out, n);
}

// round 12
// speedup vs baseline: 1.0492x; 1.0203x over previous
#include <cuda_runtime.h>
#include <cuda_bf16.h>

// Pendulum RK4 trajectory, N=200000, T=100. out[N][T][2] fp32.
// R2:  297us scalar strided stores (L1tex wavefront bound)
// R4:  46.9us smem transpose stores; 40 regs, SINGLE WAVE -> issue 77.9%
// R8:  39.1us 16-step unroll; regs 64 -> 1.32 waves -> issue 65.5%
// R9:  39.6us lb(256,5); 740 resident < 782 -> 1.06 waves -> issue 67.8%
// R10/11: ILP2 caps total warps at 21/SM (33% occ) — dead end.
// KEY: issued work is ~constant 25-27us-equiv since R8; dur = work/issue%,
//      and issue% tracks wave balance. R12: ILP1, 128-thr blocks,
//      lb(128,11) => 1628-block capacity >= 1563-block grid = ONE wave,
//      44 warps/SM. unroll 4 + 8-slot chunks to fit 45 regs.

#define PEND_T 100
#define PEND_G 10.0f
#define ROWF2  10           // 8 slots + pad, 80B pitch (16B-aligned rows)
#define NWARPS 4            // 128 threads

__device__ __forceinline__ void rk4_step(float& theta, float& omega,
                                         float coef, float4 d)
{
    const float dt = d.x, dt3 = d.y, dt8 = d.z;
    const float third = 1.0f / 3.0f;

    const float k1t = omega;
    const float k1w = coef * __sinf(theta);

    const float y2t = fmaf(dt3, k1t, theta);
    const float y2w = fmaf(dt3, k1w, omega);
    const float k2t = y2w;
    const float k2w = coef * __sinf(y2t);

    const float e3t = fmaf(-third, k1t, k2t);      // k2 - k1/3
    const float e3w = fmaf(-third, k1w, k2w);
    const float y3t = fmaf(dt, e3t, theta);
    const float y3w = fmaf(dt, e3w, omega);
    const float k3t = y3w;
    const float k3w = coef * __sinf(y3t);

    const float e4t = (k1t - k2t) + k3t;           // k1 - k2 + k3
    const float e4w = (k1w - k2w) + k3w;
    const float y4t = fmaf(dt, e4t, theta);
    const float y4w = fmaf(dt, e4w, omega);
    const float k4t = y4w;
    const float k4w = coef * __sinf(y4t);

    const float st = fmaf(3.0f, k2t + k3t, k1t) + k4t;   // k1+3(k2+k3)+k4
    const float sw = fmaf(3.0f, k2w + k3w, k1w) + k4w;
    theta = fmaf(dt8, st, theta);
    omega = fmaf(dt8, sw, omega);
}

// Flush one 8-slot chunk: 32 particles x 4 float4, 4 lanes per particle,
// fully coalesced STG.128 (each particle chunk = 64B contiguous).
__device__ __forceinline__ void flush8(const float2 (* __restrict__ mybuf)[ROWF2],
                                       float4* __restrict__ out4,
                                       size_t rowbase, int lane, int base)
{
    __syncwarp();
    #pragma unroll
    for (int j = 0; j < 4; j++) {
        const int idx = j * 32 + lane;
        const int p   = idx >> 2;          // particle within warp (0..31)
        const int s4  = idx & 3;           // float4 slot within chunk
        const float4 v = *reinterpret_cast<const float4*>(&mybuf[p][s4 * 2]);
        out4[rowbase + (size_t)p * (PEND_T / 2) + (base >> 1) + s4] = v;
    }
    __syncwarp();
}

__global__ __launch_bounds__(128, 11) void pendulum_rk4_kernel(
    const float* __restrict__ t,
    const float* __restrict__ z0,
    const float* __restrict__ params,
    float* __restrict__ out,
    int n)
{
    __shared__ __align__(16) float4 sdt4[PEND_T - 1];        // {dt, dt/3, dt/8, -}
    __shared__ __align__(16) float2 buf[NWARPS][32][ROWF2];  // 10.2KB

    for (int j = threadIdx.x; j < PEND_T - 1; j += blockDim.x) {
        const float d = t[j + 1] - t[j];
        sdt4[j] = make_float4(d, d * (1.0f / 3.0f), d * 0.125f, 0.0f);
    }
    __syncthreads();

    const int warp = threadIdx.x >> 5;
    const int lane = threadIdx.x & 31;
    const int warpbase = blockIdx.x * blockDim.x + warp * 32;
    if (warpbase >= n) return;            // n multiple of 32: whole warps only

    float2 (* __restrict__ mybuf)[ROWF2] = buf[warp];

    const int i = warpbase + lane;
    const float2 z = reinterpret_cast<const float2*>(z0)[i];
    float theta = z.x;
    float omega = z.y;
    const float coef = -(PEND_G / params[i]);

    float4* __restrict__ out4 = reinterpret_cast<float4*>(out);
    const size_t rowbase = (size_t)warpbase * (PEND_T / 2);   // 50 float4/row

    // ---- chunk 0: slot 0 (initial state) + steps 1..7 ----
    mybuf[lane][0] = make_float2(theta, omega);
    #pragma unroll 4
    for (int k = 1; k < 8; k++) {
        rk4_step(theta, omega, coef, sdt4[k - 1]);
        mybuf[lane][k] = make_float2(theta, omega);
    }
    flush8(mybuf, out4, rowbase, lane, 0);

    // ---- chunks 1..11: 8 steps each ----
    #pragma unroll 1
    for (int c = 1; c < 12; c++) {
        const int base = c * 8;
        #pragma unroll 4
        for (int k = 0; k < 8; k++) {
            rk4_step(theta, omega, coef, sdt4[base - 1 + k]);
            mybuf[lane][k] = make_float2(theta, omega);
        }
        flush8(mybuf, out4, rowbase, lane, base);
    }

    // ---- tail: steps 96..99 (4 slots = 2 float4 per particle) ----
    #pragma unroll
    for (int k = 0; k < 4; k++) {
        rk4_step(theta, omega, coef, sdt4[95 + k]);
        mybuf[lane][k] = make_float2(theta, omega);
    }
    __syncwarp();
    #pragma unroll
    for (int j = 0; j < 2; j++) {
        const int idx = j * 32 + lane;
        const int p   = idx >> 1;          // 0..31
        const int s4  = idx & 1;
        const float4 v = *reinterpret_cast<const float4*>(&mybuf[p][s4 * 2]);
        out4[rowbase + (size_t)p * (PEND_T / 2) + 48 + s4] = v;
    }
}

extern "C" void kernel_launch(void* const* d_in, const int* in_sizes, int n_in,
                              void* d_out, int out_size)
{
    (void)n_in; (void)out_size;
    // d_in[0] = mini_batch (unused), d_in[1] = t, d_in[2] = z0, d_in[3] = params
    const float* t      = (const float*)d_in[1];
    const float* z0     = (const float*)d_in[2];
    const float* params = (const float*)d_in[3];
    float* out          = (float*)d_out;

    const int n = in_sizes[3];
    const int threads = 128;
    const int blocks  = (n + threads - 1) / threads;   // 1563
    pendulum_rk4_kernel<<<blocks, threads>>>(t, z0, params, out, n);
}

// round 13
// speedup vs baseline: 1.1266x; 1.0738x over previous
#include <cuda_runtime.h>
#include <cuda_bf16.h>

// Pendulum RK4 trajectory, N=200000, T=100. out[N][T][2] fp32.
// R2:  297us scalar strided stores (L1tex wavefront bound)
// R4:  46.9us smem transpose stores, single wave -> issue 77.9%
// R8:  39.1us 16-step unroll (1.32 waves, issue 65.5%)
// R12: 41.0us (ncu 37.8) single wave, occ 50.7% but L1=73.9% -> L1tex is
//      the binder: 4-way STS conflicts + 8-line STG flushes + LDS flushes.
// R13: 128B smem rows w/ SW128 XOR swizzle (conflict-free STS/LDS),
//      2 steps packed per STS.128, 16-slot chunks so flush STG covers
//      full 128B lines. ~56 vs ~96 L1 wavefronts per 8 steps.

#define PEND_T 100
#define PEND_G 10.0f
#define NWARPS 4            // 128 threads

__device__ __forceinline__ void rk4_step(float& theta, float& omega,
                                         float coef, float4 d)
{
    const float dt = d.x, dt3 = d.y, dt8 = d.z;
    const float third = 1.0f / 3.0f;

    const float k1t = omega;
    const float k1w = coef * __sinf(theta);

    const float y2t = fmaf(dt3, k1t, theta);
    const float y2w = fmaf(dt3, k1w, omega);
    const float k2t = y2w;
    const float k2w = coef * __sinf(y2t);

    const float e3t = fmaf(-third, k1t, k2t);      // k2 - k1/3
    const float e3w = fmaf(-third, k1w, k2w);
    const float y3t = fmaf(dt, e3t, theta);
    const float y3w = fmaf(dt, e3w, omega);
    const float k3t = y3w;
    const float k3w = coef * __sinf(y3t);

    const float e4t = (k1t - k2t) + k3t;           // k1 - k2 + k3
    const float e4w = (k1w - k2w) + k3w;
    const float y4t = fmaf(dt, e4t, theta);
    const float y4w = fmaf(dt, e4w, omega);
    const float k4t = y4w;
    const float k4w = coef * __sinf(y4t);

    const float st = fmaf(3.0f, k2t + k3t, k1t) + k4t;   // k1+3(k2+k3)+k4
    const float sw = fmaf(3.0f, k2w + k3w, k1w) + k4w;
    theta = fmaf(dt8, st, theta);
    omega = fmaf(dt8, sw, omega);
}

// Store a pair of slots (even,odd) as one swizzled STS.128.
// tile row = 128B per lane; swizzle: column c16 ^= (lane&7)<<4.
__device__ __forceinline__ void stpair(char* tile, int lanebase, int xsw,
                                       int c, float pt, float pw,
                                       float ct, float cw)
{
    *reinterpret_cast<float4*>(tile + lanebase + ((c * 16) ^ xsw)) =
        make_float4(pt, pw, ct, cw);
}

// Flush a 16-slot chunk: 32 particles x 8 float4. 8 lanes per particle
// cover one full 128B output line. Swizzled conflict-free LDS.128.
__device__ __forceinline__ void flush16(const char* tile,
                                        float4* __restrict__ out4,
                                        size_t rowbase, int lane, int base)
{
    __syncwarp();
    const int p0 = lane >> 3;          // 0..3
    const int s4 = lane & 7;           // 0..7
    #pragma unroll
    for (int j = 0; j < 8; j++) {
        const int p   = 4 * j + p0;    // particle 0..31
        const int off = p * 128 + ((s4 * 16) ^ ((p & 7) << 4));
        const float4 v = *reinterpret_cast<const float4*>(tile + off);
        out4[rowbase + (size_t)p * (PEND_T / 2) + (base >> 1) + s4] = v;
    }
    __syncwarp();
}

__global__ __launch_bounds__(128, 11) void pendulum_rk4_kernel(
    const float* __restrict__ t,
    const float* __restrict__ z0,
    const float* __restrict__ params,
    float* __restrict__ out,
    int n)
{
    __shared__ __align__(16) float4 sdt4[PEND_T - 1];     // {dt, dt/3, dt/8, -}
    __shared__ alignas(128) char smem_buf[NWARPS * 32 * 128];   // 16KB

    for (int j = threadIdx.x; j < PEND_T - 1; j += blockDim.x) {
        const float d = t[j + 1] - t[j];
        sdt4[j] = make_float4(d, d * (1.0f / 3.0f), d * 0.125f, 0.0f);
    }
    __syncthreads();

    const int warp = threadIdx.x >> 5;
    const int lane = threadIdx.x & 31;
    const int warpbase = blockIdx.x * blockDim.x + warp * 32;
    if (warpbase >= n) return;            // n multiple of 32: whole warps only

    char* tile = smem_buf + warp * 4096;
    const int lanebase = lane * 128;
    const int xsw = (lane & 7) << 4;

    const int i = warpbase + lane;
    const float2 z = reinterpret_cast<const float2*>(z0)[i];
    float theta = z.x;
    float omega = z.y;
    const float coef = -(PEND_G / params[i]);

    float4* __restrict__ out4 = reinterpret_cast<float4*>(out);
    const size_t rowbase = (size_t)warpbase * (PEND_T / 2);   // 50 float4/row

    // ---- chunk 0: pair 0 = (initial state, step 1), pairs 1..7 ----
    {
        float pt = theta, pw = omega;
        rk4_step(theta, omega, coef, sdt4[0]);
        stpair(tile, lanebase, xsw, 0, pt, pw, theta, omega);
        #pragma unroll 2
        for (int c = 1; c < 8; c++) {
            rk4_step(theta, omega, coef, sdt4[2 * c - 1]);
            pt = theta; pw = omega;
            rk4_step(theta, omega, coef, sdt4[2 * c]);
            stpair(tile, lanebase, xsw, c, pt, pw, theta, omega);
        }
        flush16(tile, out4, rowbase, lane, 0);
    }

    // ---- chunks 1..5: 16 steps each ----
    #pragma unroll 1
    for (int ch = 1; ch < 6; ch++) {
        const int base = ch * 16;
        #pragma unroll 2
        for (int c = 0; c < 8; c++) {
            rk4_step(theta, omega, coef, sdt4[base + 2 * c - 1]);
            const float pt = theta, pw = omega;
            rk4_step(theta, omega, coef, sdt4[base + 2 * c]);
            stpair(tile, lanebase, xsw, c, pt, pw, theta, omega);
        }
        flush16(tile, out4, rowbase, lane, base);
    }

    // ---- tail: slots 96..99 (2 pairs) ----
    #pragma unroll
    for (int c = 0; c < 2; c++) {
        rk4_step(theta, omega, coef, sdt4[95 + 2 * c]);
        const float pt = theta, pw = omega;
        rk4_step(theta, omega, coef, sdt4[96 + 2 * c]);
        stpair(tile, lanebase, xsw, c, pt, pw, theta, omega);
    }
    __syncwarp();
    {
        const int p0 = lane >> 1;          // 0..15
        const int s4 = lane & 1;           // 0..1
        #pragma unroll
        for (int j = 0; j < 2; j++) {
            const int p   = 16 * j + p0;   // particle 0..31
            const int off = p * 128 + ((s4 * 16) ^ ((p & 7) << 4));
            const float4 v = *reinterpret_cast<const float4*>(tile + off);
            out4[rowbase + (size_t)p * (PEND_T / 2) + 48 + s4] = v;
        }
    }
}

extern "C" void kernel_launch(void* const* d_in, const int* in_sizes, int n_in,
                              void* d_out, int out_size)
{
    (void)n_in; (void)out_size;
    // d_in[0] = mini_batch (unused), d_in[1] = t, d_in[2] = z0, d_in[3] = params
    const float* t      = (const float*)d_in[1];
    const float* z0     = (const float*)d_in[2];
    const float* params = (const float*)d_in[3];
    float* out          = (float*)d_out;

    const int n = in_sizes[3];
    const int threads = 128;
    const int blocks  = (n + threads - 1) / threads;   // 1563 -> single wave
    pendulum_rk4_kernel<<<blocks, threads>>>(t, z0, params, out, n);
}